// round 17
// baseline (speedup 1.0000x reference)
#include <cuda_runtime.h>
#include <math.h>

#define V 720
#define QV 180
#define U 736
#define NXY 512
#define NPIX (NXY * NXY)
#define NTAPS 368

#define DU_D   1.2858
#define DSO_D  595.0
#define DOD_D  490.6
#define DSD_D  (DSO_D + DOD_D)
#define SVOX_D 400.0
#define PI_D   3.14159265358979323846

// parity-packed conv arrays
#define PADE 380
#define PODD 383
#define WLEN 1124

// guard-band padded filtered rows: slot i holds detector index u = i - QPAD
#define QPAD 512
#define QSTRIDE 1760            // 512 + 736 + 512

// ---- device-global scratch ----
__device__ float4 g_trig[V];          // (cb*DSD/DU, sb*DSD/DU, cb, sb)
__device__ float2 g_Qp[V * QSTRIDE];  // (Q[u], Q[u+1]-Q[u]); (0,0) outside [0,U-2]
__device__ float  g_accS[NPIX];       // views   0..179 -> pixel P
__device__ float  g_acc90[NPIX];      // views 180..359 -> rot90(P)
__device__ float  g_acc180[NPIX];     // views 360..539 -> -P
__device__ float  g_acc270[NPIX];     // views 540..719 -> rot270(P)

// ---------------------------------------------------------------------------
// Kernel 1: cosine weight + Ram-Lak conv, parity-packed + register-tiled,
// split left/right tap loops bounded per warp (skip guaranteed-zero taps).
// ---------------------------------------------------------------------------
__global__ __launch_bounds__(192) void filter_kernel(const float* __restrict__ sino) {
    __shared__ __align__(16) float wo_s[WLEN];
    __shared__ __align__(16) float we_s[WLEN];
    __shared__ __align__(16) float ho_s[NTAPS];
    __shared__ float qrow[U];

    const int v = blockIdx.x;
    const int tid = threadIdx.x;

    for (int i = tid; i < WLEN; i += 192) { wo_s[i] = 0.0f; we_s[i] = 0.0f; }
    for (int k = tid; k < NTAPS; k += 192) {
        float d = (float)(PI_D * DU_D) * (float)(2 * k + 1);
        ho_s[k] = -1.0f / (d * d);
    }
    if (tid == 0) {
        float bf = (float)(2.0 * PI_D * (double)v / (double)V);
        float cb = (float)cos((double)bf);
        float sb = (float)sin((double)bf);
        float kk = (float)(DSD_D / DU_D);
        g_trig[v] = make_float4(cb * kk, sb * kk, cb, sb);
    }
    __syncthreads();

    {
        const float* row = sino + v * U;
        const float dsd  = (float)DSD_D;
        const float dsd2 = (float)(DSD_D * DSD_D);
        const float du   = (float)DU_D;
        for (int u = tid; u < U; u += 192) {
            float us = ((float)u - 367.5f) * du;
            float w = row[u] * (dsd * rsqrtf(dsd2 + us * us));
            if (u & 1) wo_s[PADE + (u >> 1)] = w;
            else       we_s[PODD + (u >> 1)] = w;
        }
    }
    __syncthreads();

    const int grp = tid / 96;
    const int t   = tid % 96;
    const int wi  = t >> 5;
    if (t < 92) {
        const int b = 4 * t;
        const float* A = grp ? (we_s + PODD + 1) : (wo_s + PADE);
        const float* C = grp ? (wo_s + PADE)     : (we_s + PODD);
        const float h0 = (float)(1.0 / (4.0 * DU_D * DU_D));

        float acc0 = h0 * C[b + 0];
        float acc1 = h0 * C[b + 1];
        float acc2 = h0 * C[b + 2];
        float acc3 = h0 * C[b + 3];

        const int JL = min(32 * wi + 32, 92);
        const int JR = 92 - 32 * wi;

        {
            float4 Llo = *(const float4*)(A + b - 4);
            float4 Lhi = *(const float4*)(A + b);
            #pragma unroll 4
            for (int j = 0; j < JL; j++) {
                float4 h4 = *(const float4*)(ho_s + 4 * j);
                acc0 += h4.x * Llo.w;
                acc1 += h4.x * Lhi.x;
                acc2 += h4.x * Lhi.y;
                acc3 += h4.x * Lhi.z;
                acc0 += h4.y * Llo.z;
                acc1 += h4.y * Llo.w;
                acc2 += h4.y * Lhi.x;
                acc3 += h4.y * Lhi.y;
                acc0 += h4.z * Llo.y;
                acc1 += h4.z * Llo.z;
                acc2 += h4.z * Llo.w;
                acc3 += h4.z * Lhi.x;
                acc0 += h4.w * Llo.x;
                acc1 += h4.w * Llo.y;
                acc2 += h4.w * Llo.z;
                acc3 += h4.w * Llo.w;
                Lhi = Llo;
                Llo = *(const float4*)(A + b - 4 * j - 8);
            }
        }
        {
            float4 rlo = *(const float4*)(A + b);
            float4 rhi = *(const float4*)(A + b + 4);
            #pragma unroll 4
            for (int j = 0; j < JR; j++) {
                float4 h4 = *(const float4*)(ho_s + 4 * j);
                acc0 += h4.x * rlo.x;
                acc1 += h4.x * rlo.y;
                acc2 += h4.x * rlo.z;
                acc3 += h4.x * rlo.w;
                acc0 += h4.y * rlo.y;
                acc1 += h4.y * rlo.z;
                acc2 += h4.y * rlo.w;
                acc3 += h4.y * rhi.x;
                acc0 += h4.z * rlo.z;
                acc1 += h4.z * rlo.w;
                acc2 += h4.z * rhi.x;
                acc3 += h4.z * rhi.y;
                acc0 += h4.w * rlo.w;
                acc1 += h4.w * rhi.x;
                acc2 += h4.w * rhi.y;
                acc3 += h4.w * rhi.z;
                rlo = rhi;
                rhi = *(const float4*)(A + b + 4 * j + 8);
            }
        }

        const float du = (float)DU_D;
        const int u0 = 8 * t + grp;
        qrow[u0 + 0] = du * acc0;
        qrow[u0 + 2] = du * acc1;
        qrow[u0 + 4] = du * acc2;
        qrow[u0 + 6] = du * acc3;
    }
    __syncthreads();

    // padded (q, dq) pairs: slot i <-> u = i - QPAD; (0,0) outside [0, U-2].
    {
        float2* dst = g_Qp + v * QSTRIDE;
        for (int i = tid; i < QSTRIDE; i += 192) {
            int s = i - QPAD;
            bool in = (s >= 0) && (s <= U - 2);
            float q0 = in ? qrow[s] : 0.0f;
            float q1 = in ? qrow[s + 1] : 0.0f;
            dst[i] = make_float2(q0, q1 - q0);
        }
    }
}

// ---------------------------------------------------------------------------
// Kernel 2: 4-fold symmetric backprojection, views 0..179, 2 pixels/thread.
// Thread owns (ix0, iy) and (ix0+8, iy): 8 independent LDG.64 per iter,
// per-view overhead (LDS/ptr/loop) amortized over 2 pixels.
// Block (32,8) covers 32(iy) x 16(ix); grid 16x32 = 512 blocks = ONE wave.
// ---------------------------------------------------------------------------
#define M23 8388608.0f                       // 2^23
#define ADDR_BIAS 0x258000000ULL             // 0x4B000000 * sizeof(float2)
#define ROWB ((unsigned long long)QSTRIDE * 8ULL)
#define R180B (180ULL * ROWB)                // 2,534,400 bytes

__global__ __launch_bounds__(256, 4) void bp_kernel() {
    __shared__ __align__(16) float4 strig[QV];

    const int tid = threadIdx.y * 32 + threadIdx.x;
    for (int i = tid; i < QV; i += 256) strig[i] = g_trig[i];
    __syncthreads();

    const int iy  = blockIdx.x * 32 + threadIdx.x;
    const int ix0 = blockIdx.y * 16 + threadIdx.y;   // second pixel: ix0 + 8

    const float dx  = (float)(SVOX_D / (double)NXY);
    const float y   = ((float)iy  - 255.5f) * dx;
    const float x0  = ((float)ix0 - 255.5f) * dx;
    const float stp = 8.0f * dx;
    const float c0  = 367.5f + (float)QPAD;
    const float dso = (float)DSO_D;

    unsigned long long pa = (unsigned long long)(const char*)g_Qp - ADDR_BIAS;

    float aS0 = 0.0f, a90_0 = 0.0f, a180_0 = 0.0f, a270_0 = 0.0f;
    float aS1 = 0.0f, a90_1 = 0.0f, a180_1 = 0.0f, a270_1 = 0.0f;

    #pragma unroll 2
    for (int v = 0; v < QV; v++, pa += ROWB) {
        float4 tg = strig[v];

        float t0 = fmaf(x0, tg.x, y * tg.y);
        float t1 = fmaf(stp, tg.x, t0);
        float D0 = fmaf(x0, tg.w, fmaf(-y, tg.z, dso));
        float D1 = fmaf(stp, tg.w, D0);

        float r0, r1;
        asm("rcp.approx.f32 %0, %1;" : "=f"(r0) : "f"(D0));
        asm("rcp.approx.f32 %0, %1;" : "=f"(r1) : "f"(D1));

        float i0 = fmaf(t0, r0, c0);
        float i1 = fmaf(t1, r1, c0);
        float m0 = __fadd_rd(i0, M23);
        float m1 = __fadd_rd(i1, M23);

        unsigned long long a0 = pa + (unsigned long long)__float_as_uint(m0) * 8ULL;
        unsigned long long a1 = pa + (unsigned long long)__float_as_uint(m1) * 8ULL;

        float2 p0q0 = __ldg((const float2*)a0);
        float2 p0q1 = __ldg((const float2*)(a0 + R180B));
        float2 p0q2 = __ldg((const float2*)(a0 + 2ULL * R180B));
        float2 p0q3 = __ldg((const float2*)(a0 + 3ULL * R180B));
        float2 p1q0 = __ldg((const float2*)a1);
        float2 p1q1 = __ldg((const float2*)(a1 + R180B));
        float2 p1q2 = __ldg((const float2*)(a1 + 2ULL * R180B));
        float2 p1q3 = __ldg((const float2*)(a1 + 3ULL * R180B));

        float f0 = i0 - (m0 - M23);
        float f1 = i1 - (m1 - M23);
        float w0 = r0 * r0;
        float w1 = r1 * r1;

        aS0    = fmaf(fmaf(f0, p0q0.y, p0q0.x), w0, aS0);
        a90_0  = fmaf(fmaf(f0, p0q1.y, p0q1.x), w0, a90_0);
        a180_0 = fmaf(fmaf(f0, p0q2.y, p0q2.x), w0, a180_0);
        a270_0 = fmaf(fmaf(f0, p0q3.y, p0q3.x), w0, a270_0);
        aS1    = fmaf(fmaf(f1, p1q0.y, p1q0.x), w1, aS1);
        a90_1  = fmaf(fmaf(f1, p1q1.y, p1q1.x), w1, a90_1);
        a180_1 = fmaf(fmaf(f1, p1q2.y, p1q2.x), w1, a180_1);
        a270_1 = fmaf(fmaf(f1, p1q3.y, p1q3.x), w1, a270_1);
    }

    const int p0 = ix0 * NXY + iy;
    const int p1 = (ix0 + 8) * NXY + iy;
    g_accS[p0]   = aS0;    g_accS[p1]   = aS1;
    g_acc90[p0]  = a90_0;  g_acc90[p1]  = a90_1;
    g_acc180[p0] = a180_0; g_acc180[p1] = a180_1;
    g_acc270[p0] = a270_0; g_acc270[p1] = a270_1;
}

// ---------------------------------------------------------------------------
// Kernel 3: combine. For output O=(ix,iy):
//   out[O] = scale * ( S[O] + acc90[rot270(O)] + acc180[-O] + acc270[rot90(O)] )
// rot90(ix,iy)=(511-iy,ix); rot270(ix,iy)=(iy,511-ix); -O = (511-ix,511-iy).
// ---------------------------------------------------------------------------
__global__ __launch_bounds__(256) void combine_kernel(float* __restrict__ out) {
    const int i = blockIdx.x * 256 + threadIdx.x;
    const int ix = i >> 9;
    const int iy = i & 511;
    const float scale = (float)(0.5 * (2.0 * PI_D / (double)V) * DSO_D * DSO_D);

    float s   = g_accS[i];
    float a18 = g_acc180[NPIX - 1 - i];
    float a9  = g_acc90[iy * NXY + (NXY - 1 - ix)];    // P = rot270(O)
    float a27 = g_acc270[(NXY - 1 - iy) * NXY + ix];   // P = rot90(O)

    out[i] = (s + a9 + a18 + a27) * scale;
}

// ---------------------------------------------------------------------------
extern "C" void kernel_launch(void* const* d_in, const int* in_sizes, int n_in,
                              void* d_out, int out_size) {
    (void)in_sizes; (void)n_in; (void)out_size;
    const float* sino = (const float*)d_in[0];
    float* out = (float*)d_out;

    filter_kernel<<<V, 192>>>(sino);
    dim3 bpBlock(32, 8);
    dim3 bpGrid(NXY / 32, NXY / 16);    // 16 x 32 = 512 blocks (one wave)
    bp_kernel<<<bpGrid, bpBlock>>>();
    combine_kernel<<<NPIX / 256, 256>>>(out);
}